// round 3
// baseline (speedup 1.0000x reference)
#include <cuda_runtime.h>

#define NN 51200
#define EE 819200
#define NQ 512
#define HH 128
#define RR 16
#define NBASE 8
#define CIN 128
#define UCOLS 1152   /* (1 + NBASE) * HH : [root | bases0..7] */
#define TCOLS 2048   /* RR * HH */

// ---------------- device scratch (static; no runtime allocation) ----------------
__device__ float g_h0[NN * CIN];
__device__ float g_h1[NN * CIN];
__device__ float g_u[(size_t)NN * UCOLS];   // ~236 MB
__device__ float g_t[(size_t)NN * TCOLS];   // ~419 MB
__device__ float g_Ball[CIN * UCOLS];
__device__ float g_invcnt[NN * RR];
__device__ int   g_cnt[NN * RR];
__device__ int   g_deg[NN];
__device__ int   g_rowptr[NN + 1];
__device__ int   g_cursor[NN];
__device__ int   g_eidx[EE];
__device__ int   g_srow[EE];   // src*RR + etype, in dst-CSR sorted order
__device__ float g_ew[EE];     // 1/cnt weight per sorted edge

// ---------------- h0 = [x | one_hot(node_ent)] ----------------
__global__ void k_build_h0(const float* __restrict__ x, const int* __restrict__ ent) {
    int gid = blockIdx.x * blockDim.x + threadIdx.x;
    if (gid >= NN * CIN) return;
    int n = gid >> 7, j = gid & 127;
    float v;
    if (j < 64) v = __ldg(x + n * 64 + j);
    else        v = (__ldg(ent + n) == (j - 64)) ? 1.0f : 0.0f;
    g_h0[gid] = v;
}

// ---------------- per-(dst,rel) counts + in-degree ----------------
__global__ void k_count(const int* __restrict__ edst, const int* __restrict__ etyp) {
    int e = blockIdx.x * blockDim.x + threadIdx.x;
    if (e >= EE) return;
    int d = edst[e], t = etyp[e];
    atomicAdd(&g_cnt[d * RR + t], 1);
    atomicAdd(&g_deg[d], 1);
}

__global__ void k_invcnt() {
    int gid = blockIdx.x * blockDim.x + threadIdx.x;
    if (gid >= NN * RR) return;
    int c = g_cnt[gid];
    g_invcnt[gid] = 1.0f / (float)(c < 1 ? 1 : c);
}

// ---------------- exclusive scan of degrees (single block, 1024 threads) ----------------
__global__ void k_scan() {
    __shared__ int sdata[1024];
    __shared__ int carry;
    int tid = threadIdx.x;
    if (tid == 0) { carry = 0; g_rowptr[0] = 0; }
    __syncthreads();
    for (int base = 0; base < NN; base += 1024) {
        int v = g_deg[base + tid];
        sdata[tid] = v;
        __syncthreads();
        for (int off = 1; off < 1024; off <<= 1) {
            int t = (tid >= off) ? sdata[tid - off] : 0;
            __syncthreads();
            sdata[tid] += t;
            __syncthreads();
        }
        int incl = sdata[tid];
        g_rowptr[base + tid + 1] = carry + incl;
        g_cursor[base + tid]     = carry + incl - v;
        __syncthreads();
        if (tid == 1023) carry += incl;
        __syncthreads();
    }
}

__global__ void k_fill(const int* __restrict__ edst) {
    int e = blockIdx.x * blockDim.x + threadIdx.x;
    if (e >= EE) return;
    int pos = atomicAdd(&g_cursor[edst[e]], 1);
    g_eidx[pos] = e;
}

// deterministic per-bucket order: sort each bucket by edge id, then finalize payload
__global__ void k_sortfin(const int* __restrict__ esrc, const int* __restrict__ etyp) {
    int n = blockIdx.x * blockDim.x + threadIdx.x;
    if (n >= NN) return;
    int s = g_rowptr[n], t = g_rowptr[n + 1];
    for (int i = s + 1; i < t; i++) {
        int v = g_eidx[i];
        int j = i - 1;
        while (j >= s && g_eidx[j] > v) { g_eidx[j + 1] = g_eidx[j]; j--; }
        g_eidx[j + 1] = v;
    }
    for (int i = s; i < t; i++) {
        int e  = g_eidx[i];
        int et = etyp[e];
        g_srow[i] = esrc[e] * RR + et;
        g_ew[i]   = g_invcnt[n * RR + et];
    }
}

// ---------------- assemble B = [root | bases0..7], row-major [CIN x UCOLS] ----------------
__global__ void k_buildB(const float* __restrict__ root, const float* __restrict__ bases) {
    int gid = blockIdx.x * blockDim.x + threadIdx.x;
    if (gid >= CIN * UCOLS) return;
    int k = gid / UCOLS, c = gid - k * UCOLS;
    float v;
    if (c < HH) v = root[k * HH + c];
    else {
        int b = (c - HH) >> 7, j = c & 127;
        v = bases[((size_t)b * CIN + k) * HH + j];
    }
    g_Ball[gid] = v;
}

// ---------------- SGEMM: g_u = relu?(A) @ g_Ball, A:[NN x 128], B:[128 x 1152] ----------------
__global__ void __launch_bounds__(256) k_gemm(const float* __restrict__ A, int relu) {
    const int K = CIN, LDB = UCOLS;
    __shared__ float As[16][132];
    __shared__ float Bs[16][128];
    int tid  = threadIdx.x;
    int row0 = blockIdx.y * 128, col0 = blockIdx.x * 128;
    float acc[8][8];
#pragma unroll
    for (int i = 0; i < 8; i++)
#pragma unroll
        for (int j = 0; j < 8; j++) acc[i][j] = 0.f;
    int trow = (tid >> 4) * 8, tcol = (tid & 15) * 8;
    for (int k0 = 0; k0 < K; k0 += 16) {
#pragma unroll
        for (int i = 0; i < 2; i++) {
            int idx = tid + i * 256;
            int ar = idx >> 2, akk = (idx & 3) * 4;
            float4 v = *(const float4*)(A + (size_t)(row0 + ar) * K + k0 + akk);
            if (relu) {
                v.x = fmaxf(v.x, 0.f); v.y = fmaxf(v.y, 0.f);
                v.z = fmaxf(v.z, 0.f); v.w = fmaxf(v.w, 0.f);
            }
            As[akk + 0][ar] = v.x; As[akk + 1][ar] = v.y;
            As[akk + 2][ar] = v.z; As[akk + 3][ar] = v.w;
        }
#pragma unroll
        for (int i = 0; i < 2; i++) {
            int idx = tid + i * 256;
            int br = idx >> 5, bc = (idx & 31) * 4;
            *(float4*)&Bs[br][bc] = *(const float4*)(g_Ball + (size_t)(k0 + br) * LDB + col0 + bc);
        }
        __syncthreads();
#pragma unroll
        for (int kk = 0; kk < 16; kk++) {
            float a[8], b[8];
#pragma unroll
            for (int i = 0; i < 8; i++) a[i] = As[kk][trow + i];
#pragma unroll
            for (int j = 0; j < 8; j++) b[j] = Bs[kk][tcol + j];
#pragma unroll
            for (int i = 0; i < 8; i++)
#pragma unroll
                for (int j = 0; j < 8; j++) acc[i][j] += a[i] * b[j];
        }
        __syncthreads();
    }
#pragma unroll
    for (int i = 0; i < 8; i++)
#pragma unroll
        for (int j = 0; j < 8; j += 4) {
            float4 o = make_float4(acc[i][j], acc[i][j + 1], acc[i][j + 2], acc[i][j + 3]);
            *(float4*)(g_u + (size_t)(row0 + trow + i) * LDB + col0 + tcol + j) = o;
        }
}

// ---------------- expand: t[n,r,:] = sum_b comp[r,b] * u[n, basis b, :] ----------------
__global__ void k_expand(const float* __restrict__ comp) {
    __shared__ float sc[RR * NBASE];
    int tid = threadIdx.x;
    if (tid < RR * NBASE) sc[tid] = comp[tid];
    __syncthreads();
    int gid = blockIdx.x * blockDim.x + tid;
    int n = gid >> 7, j = gid & 127;
    const float* up = g_u + (size_t)n * UCOLS + HH + j;
    float ub[NBASE];
#pragma unroll
    for (int b = 0; b < NBASE; b++) ub[b] = up[b * HH];
    float* tp = g_t + (size_t)n * TCOLS + j;
#pragma unroll
    for (int r = 0; r < RR; r++) {
        float s = 0.f;
#pragma unroll
        for (int b = 0; b < NBASE; b++) s += sc[r * NBASE + b] * ub[b];
        tp[r * HH] = s;
    }
}

// ---------------- gather: out[n] = u_root[n] + cbias + sum_edges w * t[src,et,:] ----------------
__global__ void k_gather(const float* __restrict__ cbias, float* __restrict__ hout) {
    int warp = (blockIdx.x * blockDim.x + threadIdx.x) >> 5;
    int lane = threadIdx.x & 31;
    if (warp >= NN) return;
    int n = warp;
    int s = g_rowptr[n], e = g_rowptr[n + 1];
    float4 acc = make_float4(0.f, 0.f, 0.f, 0.f);
    for (int i = s; i < e; i++) {
        int srow = g_srow[i];
        float w  = g_ew[i];
        float4 v = *(const float4*)(g_t + (size_t)srow * HH + lane * 4);
        acc.x += w * v.x; acc.y += w * v.y; acc.z += w * v.z; acc.w += w * v.w;
    }
    float4 r  = *(const float4*)(g_u + (size_t)n * UCOLS + lane * 4);
    float4 cb = *(const float4*)(cbias + lane * 4);
    float4 o  = make_float4(r.x + cb.x + acc.x, r.y + cb.y + acc.y,
                            r.z + cb.z + acc.z, r.w + cb.w + acc.w);
    *(float4*)(hout + (size_t)n * HH + lane * 4) = o;
}

// ---------------- head: out[q] = [h4[qo] | rel[q_rel]] @ lin_w + lin_b ----------------
__global__ void k_head(const float* __restrict__ h, const int* __restrict__ dq,
                       const int* __restrict__ qr, const int* __restrict__ ptr,
                       const float* __restrict__ rel, const float* __restrict__ w,
                       const float* __restrict__ b, float* __restrict__ out) {
    int warp = (blockIdx.x * blockDim.x + threadIdx.x) >> 5;
    int lane = threadIdx.x & 31;
    if (warp >= NQ) return;
    int qo = dq[warp] + ptr[warp];
    const float* hv = h + (size_t)qo * HH;
    const float* rv = rel + (size_t)qr[warp] * HH;
    float s0 = 0.f, s1 = 0.f;
#pragma unroll
    for (int i = 0; i < 4; i++) {
        int k = lane + 32 * i;
        float a = hv[k], c = rv[k];
        s0 += a * w[k * 2 + 0] + c * w[(HH + k) * 2 + 0];
        s1 += a * w[k * 2 + 1] + c * w[(HH + k) * 2 + 1];
    }
#pragma unroll
    for (int off = 16; off; off >>= 1) {
        s0 += __shfl_xor_sync(0xFFFFFFFFu, s0, off);
        s1 += __shfl_xor_sync(0xFFFFFFFFu, s1, off);
    }
    if (lane == 0) {
        out[warp * 2 + 0] = s0 + b[0];
        out[warp * 2 + 1] = s1 + b[1];
    }
}

// ---------------- launch ----------------
extern "C" void kernel_launch(void* const* d_in, const int* in_sizes, int n_in,
                              void* d_out, int out_size) {
    const float* x    = (const float*)d_in[0];
    const int*   ent  = (const int*)  d_in[1];
    const int*   esrc = (const int*)  d_in[2];
    const int*   edst = (const int*)  d_in[3];
    const int*   etyp = (const int*)  d_in[4];
    const int*   dq   = (const int*)  d_in[5];
    const int*   qr   = (const int*)  d_in[6];
    const int*   ptr  = (const int*)  d_in[7];
    const float* rel  = (const float*)d_in[24];
    const float* lw   = (const float*)d_in[25];
    const float* lb   = (const float*)d_in[26];
    float*       out  = (float*)d_out;

    void* p;
    cudaGetSymbolAddress(&p, g_h0);  float* h0 = (float*)p;
    cudaGetSymbolAddress(&p, g_h1);  float* h1 = (float*)p;
    cudaGetSymbolAddress(&p, g_cnt); int* cntp = (int*)p;
    cudaGetSymbolAddress(&p, g_deg); int* degp = (int*)p;

    cudaMemsetAsync(cntp, 0, sizeof(int) * NN * RR, 0);
    cudaMemsetAsync(degp, 0, sizeof(int) * NN, 0);

    k_build_h0<<<(NN * CIN + 255) / 256, 256>>>(x, ent);
    k_count<<<(EE + 255) / 256, 256>>>(edst, etyp);
    k_invcnt<<<(NN * RR + 255) / 256, 256>>>();
    k_scan<<<1, 1024>>>();
    k_fill<<<(EE + 255) / 256, 256>>>(edst);
    k_sortfin<<<(NN + 255) / 256, 256>>>(esrc, etyp);

    float* hin = h0;
    float* hout = h1;
    for (int l = 0; l < 4; l++) {
        const float* bases = (const float*)d_in[8 + 4 * l];
        const float* comp  = (const float*)d_in[9 + 4 * l];
        const float* root  = (const float*)d_in[10 + 4 * l];
        const float* cb    = (const float*)d_in[11 + 4 * l];
        k_buildB<<<(CIN * UCOLS + 255) / 256, 256>>>(root, bases);
        k_gemm<<<dim3(UCOLS / 128, NN / 128), 256>>>(hin, l > 0 ? 1 : 0);
        k_expand<<<NN * HH / 256, 256>>>(comp);
        k_gather<<<NN / 8, 256>>>(cb, hout);
        float* tmp = hin; hin = hout; hout = tmp;
    }
    k_head<<<(NQ * 32 + 255) / 256, 256>>>(hin, dq, qr, ptr, rel, lw, lb, out);
}

// round 4
// speedup vs baseline: 2.0047x; 2.0047x over previous
#include <cuda_runtime.h>
#include <cstdint>

#define NN 51200
#define EE 819200
#define NQ 512
#define HH 128
#define RR 16
#define NBASE 8
#define CIN 128
#define UC2 2176      /* 128 root cols + 16*128 relation cols */
#define TCOLS 2048    /* RR * HH */
#define NBLK 50       /* NN / 1024 */

// ---------------- device scratch (static; no runtime allocation) ----------------
__device__ float g_h0[NN * CIN];
__device__ float g_h1[NN * CIN];
__device__ float g_uroot[(size_t)NN * HH];
__device__ float g_t[(size_t)NN * TCOLS];   // ~419 MB
__device__ float g_W[CIN * UC2];
__device__ float g_invcnt[NN * RR];
__device__ int   g_cnt[NN * RR];
__device__ int   g_deg[NN];
__device__ int   g_rowptr[NN + 1];
__device__ int   g_cursor[NN];
__device__ int   g_eidx[EE];
__device__ int   g_srow[EE];   // src*RR + etype, in dst-CSR sorted order
__device__ float g_ew[EE];     // 1/cnt weight per sorted edge
// scan scratch
__device__ int   g_pscan[NN];
__device__ int   g_btot[NBLK];
__device__ int   g_boff[NBLK];
__device__ int   g_total;      // M4 after flag-scan
__device__ int   g_constNN = NN;
// layer-4 frontier
__device__ int   g_qo[NQ];
__device__ int   g_flag[NN];
__device__ int   g_aidx[NN];
__device__ int   g_nodemap[NN];
__device__ float g_h4q[NQ * HH];

// ---------------- h0 = [x | one_hot(node_ent)] ----------------
__global__ void k_build_h0(const float* __restrict__ x, const int* __restrict__ ent) {
    int gid = blockIdx.x * blockDim.x + threadIdx.x;
    if (gid >= NN * CIN) return;
    int n = gid >> 7, j = gid & 127;
    float v;
    if (j < 64) v = __ldg(x + n * 64 + j);
    else        v = (__ldg(ent + n) == (j - 64)) ? 1.0f : 0.0f;
    g_h0[gid] = v;
}

// ---------------- per-(dst,rel) counts + in-degree ----------------
__global__ void k_count(const int* __restrict__ edst, const int* __restrict__ etyp) {
    int e = blockIdx.x * blockDim.x + threadIdx.x;
    if (e >= EE) return;
    int d = edst[e], t = etyp[e];
    atomicAdd(&g_cnt[d * RR + t], 1);
    atomicAdd(&g_deg[d], 1);
}

__global__ void k_invcnt() {
    int gid = blockIdx.x * blockDim.x + threadIdx.x;
    if (gid >= NN * RR) return;
    int c = g_cnt[gid];
    g_invcnt[gid] = 1.0f / (float)(c < 1 ? 1 : c);
}

// ---------------- 3-phase scan over NN ints ----------------
__global__ void k_scanA(const int* __restrict__ in) {
    __shared__ int sd[1024];
    int b = blockIdx.x, tid = threadIdx.x;
    int gid = b * 1024 + tid;
    int v = in[gid];
    sd[tid] = v;
    __syncthreads();
    for (int off = 1; off < 1024; off <<= 1) {
        int t = (tid >= off) ? sd[tid - off] : 0;
        __syncthreads();
        sd[tid] += t;
        __syncthreads();
    }
    g_pscan[gid] = sd[tid] - v;               // exclusive within block
    if (tid == 1023) g_btot[b] = sd[tid];
}

__global__ void k_scanB() {
    if (threadIdx.x == 0) {
        int run = 0;
        for (int i = 0; i < NBLK; i++) { g_boff[i] = run; run += g_btot[i]; }
        g_total = run;
    }
}

__global__ void k_finrow() {
    int gid = blockIdx.x * blockDim.x + threadIdx.x;
    if (gid >= NN) return;
    int e = g_pscan[gid] + g_boff[gid >> 10];
    g_rowptr[gid] = e;
    g_cursor[gid] = e;
    if (gid == 0) g_rowptr[NN] = EE;
}

__global__ void k_finflag() {
    int gid = blockIdx.x * blockDim.x + threadIdx.x;
    if (gid >= NN) return;
    if (g_flag[gid]) {
        int c = g_pscan[gid] + g_boff[gid >> 10];
        g_aidx[c] = gid;
        g_nodemap[gid] = c;
    }
}

__global__ void k_fill(const int* __restrict__ edst) {
    int e = blockIdx.x * blockDim.x + threadIdx.x;
    if (e >= EE) return;
    int pos = atomicAdd(&g_cursor[edst[e]], 1);
    g_eidx[pos] = e;
}

// deterministic per-bucket order: sort each bucket by edge id, then finalize payload
__global__ void k_sortfin(const int* __restrict__ esrc, const int* __restrict__ etyp) {
    int n = blockIdx.x * blockDim.x + threadIdx.x;
    if (n >= NN) return;
    int s = g_rowptr[n], t = g_rowptr[n + 1];
    for (int i = s + 1; i < t; i++) {
        int v = g_eidx[i];
        int j = i - 1;
        while (j >= s && g_eidx[j] > v) { g_eidx[j + 1] = g_eidx[j]; j--; }
        g_eidx[j + 1] = v;
    }
    for (int i = s; i < t; i++) {
        int e  = g_eidx[i];
        int et = etyp[e];
        g_srow[i] = esrc[e] * RR + et;
        g_ew[i]   = g_invcnt[n * RR + et];
    }
}

// ---------------- layer-4 frontier ----------------
__global__ void k_qlist(const int* __restrict__ dq, const int* __restrict__ ptr) {
    int q = blockIdx.x * blockDim.x + threadIdx.x;
    if (q >= NQ) return;
    g_qo[q] = dq[q] + ptr[q];
}

__global__ void k_mark() {
    int q = blockIdx.x * blockDim.x + threadIdx.x;
    if (q >= NQ) return;
    int n = g_qo[q];
    g_flag[n] = 1;
    int s = g_rowptr[n], e = g_rowptr[n + 1];
    for (int i = s; i < e; i++) g_flag[g_srow[i] >> 4] = 1;
}

// ---------------- W_all = [root | sum_b comp[r,b]*bases[b]] : [128 x 2176] ----------------
__global__ void k_buildW(const float* __restrict__ root, const float* __restrict__ bases,
                         const float* __restrict__ comp) {
    int gid = blockIdx.x * blockDim.x + threadIdx.x;
    if (gid >= CIN * UC2) return;
    int k = gid / UC2, c = gid - k * UC2;
    float v;
    if (c < HH) v = root[k * HH + c];
    else {
        int r = (c - HH) >> 7, j = c & 127;
        v = 0.f;
#pragma unroll
        for (int b = 0; b < NBASE; b++)
            v += comp[r * NBASE + b] * bases[((size_t)b * CIN + k) * HH + j];
    }
    g_W[gid] = v;
}

// ---------------- tf32 tensor-core GEMM: [M x 128] @ g_W[128 x 2176] ----------------
// cols [0,128)   -> oroot[row*128 + c]
// cols [128,2176)-> ot[row*2048 + c-128]
__device__ __forceinline__ uint32_t f2tf32(float f) {
    uint32_t u;
    asm("cvt.rna.tf32.f32 %0, %1;" : "=r"(u) : "f"(f));
    return u;
}

__device__ __forceinline__ void mma8(float* c, const uint32_t* a, const uint32_t* b) {
    asm("mma.sync.aligned.m16n8k8.row.col.f32.tf32.tf32.f32 "
        "{%0,%1,%2,%3}, {%4,%5,%6,%7}, {%8,%9}, {%0,%1,%2,%3};"
        : "+f"(c[0]), "+f"(c[1]), "+f"(c[2]), "+f"(c[3])
        : "r"(a[0]), "r"(a[1]), "r"(a[2]), "r"(a[3]), "r"(b[0]), "r"(b[1]));
}

__global__ void __launch_bounds__(256) k_gemm_tf32(
    const float* __restrict__ A, const int* __restrict__ rowmap,
    const int* __restrict__ pM, int relu,
    float* __restrict__ oroot, float* __restrict__ ot)
{
    __shared__ uint32_t As[128][36];
    __shared__ uint32_t Bs[32][136];
    int tid = threadIdx.x;
    int wid = tid >> 5, lane = tid & 31;
    int warp_m = wid >> 2, warp_n = wid & 3;   // 2 x 4 warp grid, warp tile 64x32
    int tig = lane & 3, grp = lane >> 2;
    int col0 = blockIdx.x * 128;
    int M = *pM;

    for (int rt = blockIdx.y; rt * 128 < M; rt += gridDim.y) {
        int row0 = rt * 128;
        float acc[4][4][4];
#pragma unroll
        for (int mi = 0; mi < 4; mi++)
#pragma unroll
            for (int ni = 0; ni < 4; ni++)
#pragma unroll
                for (int k = 0; k < 4; k++) acc[mi][ni][k] = 0.f;

        for (int k0 = 0; k0 < 128; k0 += 32) {
            // stage A tile (128 rows x 32 k)
#pragma unroll
            for (int i = 0; i < 4; i++) {
                int idx = tid + i * 256;
                int r = idx >> 3, kc = (idx & 7) * 4;
                int lr = row0 + r;
                int ar = (lr < M) ? (rowmap ? rowmap[lr] : lr) : 0;
                float4 v = *(const float4*)(A + (size_t)ar * CIN + k0 + kc);
                if (relu) {
                    v.x = fmaxf(v.x, 0.f); v.y = fmaxf(v.y, 0.f);
                    v.z = fmaxf(v.z, 0.f); v.w = fmaxf(v.w, 0.f);
                }
                As[r][kc + 0] = f2tf32(v.x); As[r][kc + 1] = f2tf32(v.y);
                As[r][kc + 2] = f2tf32(v.z); As[r][kc + 3] = f2tf32(v.w);
            }
            // stage B tile (32 k x 128 cols)
#pragma unroll
            for (int i = 0; i < 4; i++) {
                int idx = tid + i * 256;
                int kr = idx >> 5, c = (idx & 31) * 4;
                float4 v = *(const float4*)(g_W + (size_t)(k0 + kr) * UC2 + col0 + c);
                Bs[kr][c + 0] = f2tf32(v.x); Bs[kr][c + 1] = f2tf32(v.y);
                Bs[kr][c + 2] = f2tf32(v.z); Bs[kr][c + 3] = f2tf32(v.w);
            }
            __syncthreads();
#pragma unroll
            for (int kk = 0; kk < 32; kk += 8) {
                uint32_t a[4][4], b[4][2];
#pragma unroll
                for (int mi = 0; mi < 4; mi++) {
                    int mr = warp_m * 64 + mi * 16 + grp;
                    a[mi][0] = As[mr][kk + tig];
                    a[mi][1] = As[mr + 8][kk + tig];
                    a[mi][2] = As[mr][kk + tig + 4];
                    a[mi][3] = As[mr + 8][kk + tig + 4];
                }
#pragma unroll
                for (int ni = 0; ni < 4; ni++) {
                    int nc = warp_n * 32 + ni * 8 + grp;
                    b[ni][0] = Bs[kk + tig][nc];
                    b[ni][1] = Bs[kk + tig + 4][nc];
                }
#pragma unroll
                for (int mi = 0; mi < 4; mi++)
#pragma unroll
                    for (int ni = 0; ni < 4; ni++)
                        mma8(acc[mi][ni], a[mi], b[ni]);
            }
            __syncthreads();
        }
        // epilogue
#pragma unroll
        for (int mi = 0; mi < 4; mi++) {
#pragma unroll
            for (int ni = 0; ni < 4; ni++) {
                int gc = col0 + warp_n * 32 + ni * 8 + 2 * tig;
                int r1 = row0 + warp_m * 64 + mi * 16 + grp;
                int r2 = r1 + 8;
                float2 v1 = make_float2(acc[mi][ni][0], acc[mi][ni][1]);
                float2 v2 = make_float2(acc[mi][ni][2], acc[mi][ni][3]);
                if (gc < HH) {
                    if (r1 < M) *(float2*)(oroot + (size_t)r1 * HH + gc) = v1;
                    if (r2 < M) *(float2*)(oroot + (size_t)r2 * HH + gc) = v2;
                } else {
                    size_t c2 = gc - HH;
                    if (r1 < M) *(float2*)(ot + (size_t)r1 * TCOLS + c2) = v1;
                    if (r2 < M) *(float2*)(ot + (size_t)r2 * TCOLS + c2) = v2;
                }
            }
        }
    }
}

// ---------------- gather: out[n] = u_root[n] + cbias + sum_edges w * t[src,et,:] ----------------
__global__ void k_gather(const float* __restrict__ cbias, float* __restrict__ hout) {
    int warp = (blockIdx.x * blockDim.x + threadIdx.x) >> 5;
    int lane = threadIdx.x & 31;
    if (warp >= NN) return;
    int n = warp;
    int s = g_rowptr[n], e = g_rowptr[n + 1];
    float4 acc = make_float4(0.f, 0.f, 0.f, 0.f);
    for (int i = s; i < e; i++) {
        int srow = g_srow[i];
        float w  = g_ew[i];
        float4 v = *(const float4*)(g_t + (size_t)srow * HH + lane * 4);
        acc.x += w * v.x; acc.y += w * v.y; acc.z += w * v.z; acc.w += w * v.w;
    }
    float4 r  = *(const float4*)(g_uroot + (size_t)n * HH + lane * 4);
    float4 cb = *(const float4*)(cbias + lane * 4);
    float4 o  = make_float4(r.x + cb.x + acc.x, r.y + cb.y + acc.y,
                            r.z + cb.z + acc.z, r.w + cb.w + acc.w);
    *(float4*)(hout + (size_t)n * HH + lane * 4) = o;
}

// layer-4 gather over 512 query nodes only (compact t/uroot rows via nodemap)
__global__ void k_gather4(const float* __restrict__ cbias) {
    int warp = (blockIdx.x * blockDim.x + threadIdx.x) >> 5;
    int lane = threadIdx.x & 31;
    if (warp >= NQ) return;
    int n = g_qo[warp];
    int s = g_rowptr[n], e = g_rowptr[n + 1];
    float4 acc = make_float4(0.f, 0.f, 0.f, 0.f);
    for (int i = s; i < e; i++) {
        int srow = g_srow[i];
        float w  = g_ew[i];
        int c = g_nodemap[srow >> 4];
        int et = srow & 15;
        float4 v = *(const float4*)(g_t + (size_t)c * TCOLS + et * HH + lane * 4);
        acc.x += w * v.x; acc.y += w * v.y; acc.z += w * v.z; acc.w += w * v.w;
    }
    int cn = g_nodemap[n];
    float4 r  = *(const float4*)(g_uroot + (size_t)cn * HH + lane * 4);
    float4 cb = *(const float4*)(cbias + lane * 4);
    float4 o  = make_float4(r.x + cb.x + acc.x, r.y + cb.y + acc.y,
                            r.z + cb.z + acc.z, r.w + cb.w + acc.w);
    *(float4*)(g_h4q + (size_t)warp * HH + lane * 4) = o;
}

// ---------------- head: out[q] = [h4q[q] | rel[q_rel]] @ lin_w + lin_b ----------------
__global__ void k_head(const int* __restrict__ qr,
                       const float* __restrict__ rel, const float* __restrict__ w,
                       const float* __restrict__ b, float* __restrict__ out) {
    int warp = (blockIdx.x * blockDim.x + threadIdx.x) >> 5;
    int lane = threadIdx.x & 31;
    if (warp >= NQ) return;
    const float* hv = g_h4q + (size_t)warp * HH;
    const float* rv = rel + (size_t)qr[warp] * HH;
    float s0 = 0.f, s1 = 0.f;
#pragma unroll
    for (int i = 0; i < 4; i++) {
        int k = lane + 32 * i;
        float a = hv[k], c = rv[k];
        s0 += a * w[k * 2 + 0] + c * w[(HH + k) * 2 + 0];
        s1 += a * w[k * 2 + 1] + c * w[(HH + k) * 2 + 1];
    }
#pragma unroll
    for (int off = 16; off; off >>= 1) {
        s0 += __shfl_xor_sync(0xFFFFFFFFu, s0, off);
        s1 += __shfl_xor_sync(0xFFFFFFFFu, s1, off);
    }
    if (lane == 0) {
        out[warp * 2 + 0] = s0 + b[0];
        out[warp * 2 + 1] = s1 + b[1];
    }
}

// ---------------- launch ----------------
extern "C" void kernel_launch(void* const* d_in, const int* in_sizes, int n_in,
                              void* d_out, int out_size) {
    const float* x    = (const float*)d_in[0];
    const int*   ent  = (const int*)  d_in[1];
    const int*   esrc = (const int*)  d_in[2];
    const int*   edst = (const int*)  d_in[3];
    const int*   etyp = (const int*)  d_in[4];
    const int*   dq   = (const int*)  d_in[5];
    const int*   qr   = (const int*)  d_in[6];
    const int*   ptr  = (const int*)  d_in[7];
    const float* rel  = (const float*)d_in[24];
    const float* lw   = (const float*)d_in[25];
    const float* lb   = (const float*)d_in[26];
    float*       out  = (float*)d_out;

    void* p;
    cudaGetSymbolAddress(&p, g_h0);      float* h0   = (float*)p;
    cudaGetSymbolAddress(&p, g_h1);      float* h1   = (float*)p;
    cudaGetSymbolAddress(&p, g_uroot);   float* ur   = (float*)p;
    cudaGetSymbolAddress(&p, g_t);       float* tt   = (float*)p;
    cudaGetSymbolAddress(&p, g_cnt);     int*   cntp = (int*)p;
    cudaGetSymbolAddress(&p, g_deg);     int*   degp = (int*)p;
    cudaGetSymbolAddress(&p, g_flag);    int*   flgp = (int*)p;
    cudaGetSymbolAddress(&p, g_aidx);    int*   aidx = (int*)p;
    cudaGetSymbolAddress(&p, g_total);   int*   pM4  = (int*)p;
    cudaGetSymbolAddress(&p, g_constNN); int*   pNN  = (int*)p;

    cudaMemsetAsync(cntp, 0, sizeof(int) * NN * RR, 0);
    cudaMemsetAsync(degp, 0, sizeof(int) * NN, 0);
    cudaMemsetAsync(flgp, 0, sizeof(int) * NN, 0);

    k_build_h0<<<(NN * CIN + 255) / 256, 256>>>(x, ent);
    k_count<<<(EE + 255) / 256, 256>>>(edst, etyp);
    k_invcnt<<<(NN * RR + 255) / 256, 256>>>();
    // rowptr = exclusive scan(deg)
    k_scanA<<<NBLK, 1024>>>(degp);
    k_scanB<<<1, 32>>>();
    k_finrow<<<(NN + 255) / 256, 256>>>();
    k_fill<<<(EE + 255) / 256, 256>>>(edst);
    k_sortfin<<<(NN + 255) / 256, 256>>>(esrc, etyp);
    // layer-4 frontier (edges static -> build once)
    k_qlist<<<2, 256>>>(dq, ptr);
    k_mark<<<2, 256>>>();
    k_scanA<<<NBLK, 1024>>>(flgp);
    k_scanB<<<1, 32>>>();
    k_finflag<<<(NN + 255) / 256, 256>>>();

    float* hin = h0;
    float* hout = h1;
    for (int l = 0; l < 3; l++) {
        const float* bases = (const float*)d_in[8 + 4 * l];
        const float* comp  = (const float*)d_in[9 + 4 * l];
        const float* root  = (const float*)d_in[10 + 4 * l];
        const float* cb    = (const float*)d_in[11 + 4 * l];
        k_buildW<<<(CIN * UC2 + 255) / 256, 256>>>(root, bases, comp);
        k_gemm_tf32<<<dim3(UC2 / 128, NN / 128), 256>>>(hin, nullptr, pNN, l > 0 ? 1 : 0, ur, tt);
        k_gather<<<NN / 8, 256>>>(cb, hout);
        float* tmp = hin; hin = hout; hout = tmp;
    }
    // layer 4: frontier only
    {
        const float* bases = (const float*)d_in[20];
        const float* comp  = (const float*)d_in[21];
        const float* root  = (const float*)d_in[22];
        const float* cb    = (const float*)d_in[23];
        k_buildW<<<(CIN * UC2 + 255) / 256, 256>>>(root, bases, comp);
        k_gemm_tf32<<<dim3(UC2 / 128, 40), 256>>>(hin, aidx, pM4, 1, ur, tt);
        k_gather4<<<(NQ * 32 + 255) / 256, 256>>>(cb);
    }
    k_head<<<(NQ * 32 + 255) / 256, 256>>>(qr, rel, lw, lb, out);
}

// round 6
// speedup vs baseline: 2.3439x; 1.1692x over previous
#include <cuda_runtime.h>
#include <cstdint>

#define NN 51200
#define EE 819200
#define NQ 512
#define HH 128
#define RR 16
#define NBASE 8
#define CIN 128
#define YC 1024       /* NBASE * HH */
#define KTOT 1152     /* CIN + YC */
#define NCHUNK 36     /* KTOT / 32 */
#define NBLK 50       /* NN / 1024 */

// dynamic smem layout (words): Ahi 2*128*36, Alo 2*128*36, Bt 2*32*136
#define SM_AHI_ST 4608
#define SM_BT_ST  4352
#define SMEMSZ ((2*4608 + 2*4608 + 2*4352) * 4)

// ---------------- device scratch (static; no runtime allocation) ----------------
__device__ float g_h0[NN * CIN];
__device__ float g_h1[NN * CIN];
__device__ float g_y[(size_t)NN * YC];     // ~210 MB
__device__ float g_y4[NQ * YC];
__device__ float g_h4q[NQ * HH];
__device__ float g_invcnt[NN * RR];
__device__ int   g_cnt[NN * RR];
__device__ int   g_deg[NN];
__device__ int   g_rowptr[NN + 1];
__device__ int   g_cursor[NN];
__device__ int   g_eidx[EE];
__device__ int   g_srow[EE];   // src*RR + etype, in dst-CSR sorted order
__device__ float g_ew[EE];     // 1/cnt weight per sorted edge
__device__ int   g_qo[NQ];
// scan scratch
__device__ int   g_pscan[NN];
__device__ int   g_btot[NBLK];
__device__ int   g_boff[NBLK];

// ---------------- h0 = [x | one_hot(node_ent)] ----------------
__global__ void k_build_h0(const float* __restrict__ x, const int* __restrict__ ent) {
    int gid = blockIdx.x * blockDim.x + threadIdx.x;
    if (gid >= NN * CIN) return;
    int n = gid >> 7, j = gid & 127;
    float v;
    if (j < 64) v = __ldg(x + n * 64 + j);
    else        v = (__ldg(ent + n) == (j - 64)) ? 1.0f : 0.0f;
    g_h0[gid] = v;
}

// ---------------- per-(dst,rel) counts + in-degree ----------------
__global__ void k_count(const int* __restrict__ edst, const int* __restrict__ etyp) {
    int e = blockIdx.x * blockDim.x + threadIdx.x;
    if (e >= EE) return;
    int d = edst[e], t = etyp[e];
    atomicAdd(&g_cnt[d * RR + t], 1);
    atomicAdd(&g_deg[d], 1);
}

__global__ void k_invcnt() {
    int gid = blockIdx.x * blockDim.x + threadIdx.x;
    if (gid >= NN * RR) return;
    int c = g_cnt[gid];
    g_invcnt[gid] = 1.0f / (float)(c < 1 ? 1 : c);
}

// ---------------- 3-phase exclusive scan over NN ints ----------------
__global__ void k_scanA(const int* __restrict__ in) {
    __shared__ int sd[1024];
    int b = blockIdx.x, tid = threadIdx.x;
    int gid = b * 1024 + tid;
    int v = in[gid];
    sd[tid] = v;
    __syncthreads();
    for (int off = 1; off < 1024; off <<= 1) {
        int t = (tid >= off) ? sd[tid - off] : 0;
        __syncthreads();
        sd[tid] += t;
        __syncthreads();
    }
    g_pscan[gid] = sd[tid] - v;
    if (tid == 1023) g_btot[b] = sd[tid];
}

__global__ void k_scanB() {
    if (threadIdx.x == 0) {
        int run = 0;
        for (int i = 0; i < NBLK; i++) { g_boff[i] = run; run += g_btot[i]; }
    }
}

__global__ void k_finrow() {
    int gid = blockIdx.x * blockDim.x + threadIdx.x;
    if (gid >= NN) return;
    int e = g_pscan[gid] + g_boff[gid >> 10];
    g_rowptr[gid] = e;
    g_cursor[gid] = e;
    if (gid == 0) g_rowptr[NN] = EE;
}

__global__ void k_fill(const int* __restrict__ edst) {
    int e = blockIdx.x * blockDim.x + threadIdx.x;
    if (e >= EE) return;
    int pos = atomicAdd(&g_cursor[edst[e]], 1);
    g_eidx[pos] = e;
}

// deterministic per-bucket order: sort each bucket by edge id, then finalize payload
__global__ void k_sortfin(const int* __restrict__ esrc, const int* __restrict__ etyp) {
    int n = blockIdx.x * blockDim.x + threadIdx.x;
    if (n >= NN) return;
    int s = g_rowptr[n], t = g_rowptr[n + 1];
    for (int i = s + 1; i < t; i++) {
        int v = g_eidx[i];
        int j = i - 1;
        while (j >= s && g_eidx[j] > v) { g_eidx[j + 1] = g_eidx[j]; j--; }
        g_eidx[j + 1] = v;
    }
    for (int i = s; i < t; i++) {
        int e  = g_eidx[i];
        int et = etyp[e];
        g_srow[i] = esrc[e] * RR + et;
        g_ew[i]   = g_invcnt[n * RR + et];
    }
}

__global__ void k_qlist(const int* __restrict__ dq, const int* __restrict__ ptr) {
    int q = blockIdx.x * blockDim.x + threadIdx.x;
    if (q >= NQ) return;
    g_qo[q] = dq[q] + ptr[q];
}

// ---------------- aggregate-first: y[n,b,:] = sum_e comp[et,b]*w * h[src,:] ----------------
__device__ __forceinline__ void aggr_node(
    const float* __restrict__ hin, const float* __restrict__ sc,
    int n, int lane, float* __restrict__ yout)
{
    int s = g_rowptr[n], e = g_rowptr[n + 1];
    float4 acc[NBASE];
#pragma unroll
    for (int b = 0; b < NBASE; b++) acc[b] = make_float4(0.f, 0.f, 0.f, 0.f);
    int i = s;
    for (; i + 2 <= e; i += 2) {
        int s0 = g_srow[i],  s1 = g_srow[i + 1];
        float w0 = g_ew[i],  w1 = g_ew[i + 1];
        float4 v0 = *(const float4*)(hin + (size_t)(s0 >> 4) * HH + (lane << 2));
        float4 v1 = *(const float4*)(hin + (size_t)(s1 >> 4) * HH + (lane << 2));
        const float* c0 = sc + (s0 & 15) * NBASE;
        const float* c1 = sc + (s1 & 15) * NBASE;
#pragma unroll
        for (int b = 0; b < NBASE; b++) {
            float f0 = c0[b] * w0;
            acc[b].x += f0 * v0.x; acc[b].y += f0 * v0.y;
            acc[b].z += f0 * v0.z; acc[b].w += f0 * v0.w;
            float f1 = c1[b] * w1;
            acc[b].x += f1 * v1.x; acc[b].y += f1 * v1.y;
            acc[b].z += f1 * v1.z; acc[b].w += f1 * v1.w;
        }
    }
    if (i < e) {
        int s0 = g_srow[i];
        float w0 = g_ew[i];
        float4 v0 = *(const float4*)(hin + (size_t)(s0 >> 4) * HH + (lane << 2));
        const float* c0 = sc + (s0 & 15) * NBASE;
#pragma unroll
        for (int b = 0; b < NBASE; b++) {
            float f0 = c0[b] * w0;
            acc[b].x += f0 * v0.x; acc[b].y += f0 * v0.y;
            acc[b].z += f0 * v0.z; acc[b].w += f0 * v0.w;
        }
    }
    float* yp = yout + (lane << 2);
#pragma unroll
    for (int b = 0; b < NBASE; b++) *(float4*)(yp + b * HH) = acc[b];
}

__global__ void __launch_bounds__(256) k_aggr(const float* __restrict__ hin,
                                              const float* __restrict__ comp,
                                              float* __restrict__ y) {
    __shared__ float sc[RR * NBASE];
    int tid = threadIdx.x;
    if (tid < RR * NBASE) sc[tid] = comp[tid];
    __syncthreads();
    int warp = (blockIdx.x * blockDim.x + tid) >> 5;
    int lane = tid & 31;
    if (warp >= NN) return;
    aggr_node(hin, sc, warp, lane, y + (size_t)warp * YC);
}

__global__ void __launch_bounds__(256) k_aggr4(const float* __restrict__ hin,
                                               const float* __restrict__ comp,
                                               float* __restrict__ y4) {
    __shared__ float sc[RR * NBASE];
    int tid = threadIdx.x;
    if (tid < RR * NBASE) sc[tid] = comp[tid];
    __syncthreads();
    int warp = (blockIdx.x * blockDim.x + tid) >> 5;
    int lane = tid & 31;
    if (warp >= NQ) return;
    aggr_node(hin, sc, g_qo[warp], lane, y4 + (size_t)warp * YC);
}

// ---------------- split-A tf32 GEMM: C = [A1 | A2] @ [Br ; Bb] + cbias (+relu) ----------------
__device__ __forceinline__ uint32_t f2tf32(float f) {
    uint32_t u;
    asm("cvt.rna.tf32.f32 %0, %1;" : "=r"(u) : "f"(f));
    return u;
}

__device__ __forceinline__ void mma8(float* c, const uint32_t* a, const uint32_t* b) {
    asm("mma.sync.aligned.m16n8k8.row.col.f32.tf32.tf32.f32 "
        "{%0,%1,%2,%3}, {%4,%5,%6,%7}, {%8,%9}, {%0,%1,%2,%3};"
        : "+f"(c[0]), "+f"(c[1]), "+f"(c[2]), "+f"(c[3])
        : "r"(a[0]), "r"(a[1]), "r"(a[2]), "r"(a[3]), "r"(b[0]), "r"(b[1]));
}

__device__ __forceinline__ void cvt4(float4 v, uint4& hi, uint4& lo) {
    hi.x = f2tf32(v.x); lo.x = f2tf32(v.x - __uint_as_float(hi.x));
    hi.y = f2tf32(v.y); lo.y = f2tf32(v.y - __uint_as_float(hi.y));
    hi.z = f2tf32(v.z); lo.z = f2tf32(v.z - __uint_as_float(hi.z));
    hi.w = f2tf32(v.w); lo.w = f2tf32(v.w - __uint_as_float(hi.w));
}

__global__ void __launch_bounds__(512) k_gemm2(
    const float* __restrict__ A1,   // [M x 128] via rowmap (or identity)
    const float* __restrict__ A2,   // [M x 1024] logical rows
    const float* __restrict__ Br,   // [128 x 128]
    const float* __restrict__ Bb,   // [1024 x 128]
    const int* __restrict__ rowmap, // nullable (A1 rows only)
    const float* __restrict__ cbias,
    float* __restrict__ Cout, int relu)
{
    extern __shared__ uint32_t sm[];
    uint32_t* Ahi = sm;                      // 2 stages x 128 x 36
    uint32_t* Alo = sm + 2 * SM_AHI_ST;
    uint32_t* Bt  = sm + 4 * SM_AHI_ST;      // 2 stages x 32 x 136

    int tid = threadIdx.x;
    int wid = tid >> 5, lane = tid & 31;
    int wm = wid >> 2, wn = wid & 3;         // 4x4 warps, warp tile 32x32
    int grp = lane >> 2, tig = lane & 3;
    int row0 = blockIdx.x * 128;

    // staging indices (2 float4 each for A and B per thread)
    int r0 = tid >> 3, r1 = r0 + 64;
    int kc = (tid & 7) * 4;
    int kr0 = tid >> 5, kr1 = kr0 + 16;
    int cB = (tid & 31) * 4;
    int a1r0 = rowmap ? rowmap[row0 + r0] : (row0 + r0);
    int a1r1 = rowmap ? rowmap[row0 + r1] : (row0 + r1);

    float4 av0, av1, bv0, bv1;

    auto LOAD = [&](int ci) {
        int k0 = ci * 32;
        if (k0 < 128) {
            av0 = *(const float4*)(A1 + (size_t)a1r0 * CIN + k0 + kc);
            av1 = *(const float4*)(A1 + (size_t)a1r1 * CIN + k0 + kc);
            bv0 = *(const float4*)(Br + (size_t)(k0 + kr0) * HH + cB);
            bv1 = *(const float4*)(Br + (size_t)(k0 + kr1) * HH + cB);
        } else {
            int k2 = k0 - 128;
            av0 = *(const float4*)(A2 + (size_t)(row0 + r0) * YC + k2 + kc);
            av1 = *(const float4*)(A2 + (size_t)(row0 + r1) * YC + k2 + kc);
            bv0 = *(const float4*)(Bb + (size_t)(k2 + kr0) * HH + cB);
            bv1 = *(const float4*)(Bb + (size_t)(k2 + kr1) * HH + cB);
        }
    };
    auto STORE = [&](int st) {
        uint4 h4, l4;
        cvt4(av0, h4, l4);
        *(uint4*)(Ahi + st * SM_AHI_ST + r0 * 36 + kc) = h4;
        *(uint4*)(Alo + st * SM_AHI_ST + r0 * 36 + kc) = l4;
        cvt4(av1, h4, l4);
        *(uint4*)(Ahi + st * SM_AHI_ST + r1 * 36 + kc) = h4;
        *(uint4*)(Alo + st * SM_AHI_ST + r1 * 36 + kc) = l4;
        uint4 b4;
        b4.x = f2tf32(bv0.x); b4.y = f2tf32(bv0.y); b4.z = f2tf32(bv0.z); b4.w = f2tf32(bv0.w);
        *(uint4*)(Bt + st * SM_BT_ST + kr0 * 136 + cB) = b4;
        b4.x = f2tf32(bv1.x); b4.y = f2tf32(bv1.y); b4.z = f2tf32(bv1.z); b4.w = f2tf32(bv1.w);
        *(uint4*)(Bt + st * SM_BT_ST + kr1 * 136 + cB) = b4;
    };

    float acc[2][4][4];
#pragma unroll
    for (int mi = 0; mi < 2; mi++)
#pragma unroll
        for (int ni = 0; ni < 4; ni++)
#pragma unroll
            for (int k = 0; k < 4; k++) acc[mi][ni][k] = 0.f;

    LOAD(0);
    STORE(0);
    __syncthreads();

    for (int ci = 0; ci < NCHUNK; ci++) {
        int st = ci & 1;
        if (ci + 1 < NCHUNK) LOAD(ci + 1);
        const uint32_t* sAh = Ahi + st * SM_AHI_ST;
        const uint32_t* sAl = Alo + st * SM_AHI_ST;
        const uint32_t* sB  = Bt  + st * SM_BT_ST;
#pragma unroll
        for (int kk = 0; kk < 32; kk += 8) {
            uint32_t bf[4][2];
#pragma unroll
            for (int ni = 0; ni < 4; ni++) {
                int nc = wn * 32 + ni * 8 + grp;
                bf[ni][0] = sB[(kk + tig) * 136 + nc];
                bf[ni][1] = sB[(kk + tig + 4) * 136 + nc];
            }
#pragma unroll
            for (int mi = 0; mi < 2; mi++) {
                int mr = wm * 32 + mi * 16 + grp;
                uint32_t ah[4], al[4];
                ah[0] = sAh[mr * 36 + kk + tig];
                ah[1] = sAh[(mr + 8) * 36 + kk + tig];
                ah[2] = sAh[mr * 36 + kk + tig + 4];
                ah[3] = sAh[(mr + 8) * 36 + kk + tig + 4];
                al[0] = sAl[mr * 36 + kk + tig];
                al[1] = sAl[(mr + 8) * 36 + kk + tig];
                al[2] = sAl[mr * 36 + kk + tig + 4];
                al[3] = sAl[(mr + 8) * 36 + kk + tig + 4];
#pragma unroll
                for (int ni = 0; ni < 4; ni++) {
                    mma8(acc[mi][ni], ah, bf[ni]);
                    mma8(acc[mi][ni], al, bf[ni]);
                }
            }
        }
        if (ci + 1 < NCHUNK) STORE((ci + 1) & 1);
        __syncthreads();
    }

    // epilogue: + cbias, optional relu
#pragma unroll
    for (int mi = 0; mi < 2; mi++) {
#pragma unroll
        for (int ni = 0; ni < 4; ni++) {
            int gc = wn * 32 + ni * 8 + 2 * tig;
            int r1r = row0 + wm * 32 + mi * 16 + grp;
            float b0 = __ldg(cbias + gc), b1 = __ldg(cbias + gc + 1);
            float c00 = acc[mi][ni][0] + b0, c01 = acc[mi][ni][1] + b1;
            float c10 = acc[mi][ni][2] + b0, c11 = acc[mi][ni][3] + b1;
            if (relu) {
                c00 = fmaxf(c00, 0.f); c01 = fmaxf(c01, 0.f);
                c10 = fmaxf(c10, 0.f); c11 = fmaxf(c11, 0.f);
            }
            *(float2*)(Cout + (size_t)r1r * HH + gc) = make_float2(c00, c01);
            *(float2*)(Cout + (size_t)(r1r + 8) * HH + gc) = make_float2(c10, c11);
        }
    }
}

// ---------------- head: out[q] = [h4q[q] | rel[q_rel]] @ lin_w + lin_b ----------------
__global__ void k_head(const int* __restrict__ qr,
                       const float* __restrict__ rel, const float* __restrict__ w,
                       const float* __restrict__ b, float* __restrict__ out) {
    int warp = (blockIdx.x * blockDim.x + threadIdx.x) >> 5;
    int lane = threadIdx.x & 31;
    if (warp >= NQ) return;
    const float* hv = g_h4q + (size_t)warp * HH;
    const float* rv = rel + (size_t)qr[warp] * HH;
    float s0 = 0.f, s1 = 0.f;
#pragma unroll
    for (int i = 0; i < 4; i++) {
        int k = lane + 32 * i;
        float a = hv[k], c = rv[k];
        s0 += a * w[k * 2 + 0] + c * w[(HH + k) * 2 + 0];
        s1 += a * w[k * 2 + 1] + c * w[(HH + k) * 2 + 1];
    }
#pragma unroll
    for (int off = 16; off; off >>= 1) {
        s0 += __shfl_xor_sync(0xFFFFFFFFu, s0, off);
        s1 += __shfl_xor_sync(0xFFFFFFFFu, s1, off);
    }
    if (lane == 0) {
        out[warp * 2 + 0] = s0 + b[0];
        out[warp * 2 + 1] = s1 + b[1];
    }
}

// ---------------- launch ----------------
extern "C" void kernel_launch(void* const* d_in, const int* in_sizes, int n_in,
                              void* d_out, int out_size) {
    const float* x    = (const float*)d_in[0];
    const int*   ent  = (const int*)  d_in[1];
    const int*   esrc = (const int*)  d_in[2];
    const int*   edst = (const int*)  d_in[3];
    const int*   etyp = (const int*)  d_in[4];
    const int*   dq   = (const int*)  d_in[5];
    const int*   qr   = (const int*)  d_in[6];
    const int*   ptr  = (const int*)  d_in[7];
    const float* rel  = (const float*)d_in[24];
    const float* lw   = (const float*)d_in[25];
    const float* lb   = (const float*)d_in[26];
    float*       out  = (float*)d_out;

    void* p;
    cudaGetSymbolAddress(&p, g_h0);   float* h0   = (float*)p;
    cudaGetSymbolAddress(&p, g_h1);   float* h1   = (float*)p;
    cudaGetSymbolAddress(&p, g_y);    float* yy   = (float*)p;
    cudaGetSymbolAddress(&p, g_y4);   float* y4   = (float*)p;
    cudaGetSymbolAddress(&p, g_h4q);  float* h4q  = (float*)p;
    cudaGetSymbolAddress(&p, g_cnt);  int*   cntp = (int*)p;
    cudaGetSymbolAddress(&p, g_deg);  int*   degp = (int*)p;
    cudaGetSymbolAddress(&p, g_qo);   int*   qop  = (int*)p;

    cudaFuncSetAttribute(k_gemm2, cudaFuncAttributeMaxDynamicSharedMemorySize, SMEMSZ);

    cudaMemsetAsync(cntp, 0, sizeof(int) * NN * RR, 0);
    cudaMemsetAsync(degp, 0, sizeof(int) * NN, 0);

    k_build_h0<<<(NN * CIN + 255) / 256, 256>>>(x, ent);
    k_count<<<(EE + 255) / 256, 256>>>(edst, etyp);
    k_invcnt<<<(NN * RR + 255) / 256, 256>>>();
    k_scanA<<<NBLK, 1024>>>(degp);
    k_scanB<<<1, 32>>>();
    k_finrow<<<(NN + 255) / 256, 256>>>();
    k_fill<<<(EE + 255) / 256, 256>>>(edst);
    k_sortfin<<<(NN + 255) / 256, 256>>>(esrc, etyp);
    k_qlist<<<2, 256>>>(dq, ptr);

    float* hin = h0;
    float* hout = h1;
    for (int l = 0; l < 3; l++) {
        const float* bases = (const float*)d_in[8 + 4 * l];
        const float* comp  = (const float*)d_in[9 + 4 * l];
        const float* root  = (const float*)d_in[10 + 4 * l];
        const float* cb    = (const float*)d_in[11 + 4 * l];
        k_aggr<<<NN / 8, 256>>>(hin, comp, yy);
        k_gemm2<<<NN / 128, 512, SMEMSZ>>>(hin, yy, root, bases, nullptr, cb, hout, 1);
        float* tmp = hin; hin = hout; hout = tmp;
    }
    // layer 4: only 512 query rows
    {
        const float* bases = (const float*)d_in[20];
        const float* comp  = (const float*)d_in[21];
        const float* root  = (const float*)d_in[22];
        const float* cb    = (const float*)d_in[23];
        k_aggr4<<<NQ / 8, 256>>>(hin, comp, y4);
        k_gemm2<<<NQ / 128, 512, SMEMSZ>>>(hin, y4, root, bases, qop, cb, h4q, 0);
    }
    k_head<<<(NQ * 32 + 255) / 256, 256>>>(qr, rel, lw, lb, out);
}

// round 7
// speedup vs baseline: 2.3673x; 1.0100x over previous
#include <cuda_runtime.h>
#include <cuda_bf16.h>
#include <cstdint>

#define NN 51200
#define EE 819200
#define NQ 512
#define HH 128
#define RR 16
#define NBASE 8
#define CIN 128
#define YC 1024       /* NBASE * HH */
#define KTOT 1152     /* CIN + YC */
#define NCHUNK 36     /* KTOT / 32 */
#define NBLK 50       /* NN / 1024 */

// smem (32-bit words): Ah/Al 2 stages x 128 rows x 20, Bh/Bl 2 stages x 16 x 136
#define ASTRIDE 20
#define A_PLANE 2560
#define B_PLANE 2176
#define OFF_AL  (2 * A_PLANE)
#define OFF_BH  (4 * A_PLANE)
#define OFF_BL  (4 * A_PLANE + 2 * B_PLANE)
#define SMEMSZ ((4 * A_PLANE + 4 * B_PLANE) * 4)   /* 75776 B */

// ---------------- device scratch (static; no runtime allocation) ----------------
__device__ float g_h0[NN * CIN];
__device__ float g_h1[NN * CIN];
__device__ float g_y[(size_t)NN * YC];     // ~210 MB
__device__ float g_y4[NQ * YC];
__device__ float g_h4q[NQ * HH];
__device__ int   g_cnt[NN * RR];
__device__ int   g_deg[NN];
__device__ int   g_rowptr[NN + 1];
__device__ int   g_cursor[NN];
__device__ int   g_eidx[EE];
__device__ int   g_srow[EE];   // src*RR + etype, in dst-CSR sorted order
__device__ float g_ew[EE];     // 1/cnt weight per sorted edge
__device__ int   g_qo[NQ];
// scan scratch
__device__ int   g_pscan[NN];
__device__ int   g_btot[NBLK];
__device__ int   g_boff[NBLK];

// ---------------- h0 = [x | one_hot(node_ent)] ----------------
__global__ void k_build_h0(const float* __restrict__ x, const int* __restrict__ ent) {
    int gid = blockIdx.x * blockDim.x + threadIdx.x;
    if (gid >= NN * CIN) return;
    int n = gid >> 7, j = gid & 127;
    float v;
    if (j < 64) v = __ldg(x + n * 64 + j);
    else        v = (__ldg(ent + n) == (j - 64)) ? 1.0f : 0.0f;
    g_h0[gid] = v;
}

// ---------------- per-(dst,rel) counts + in-degree ----------------
__global__ void k_count(const int* __restrict__ edst, const int* __restrict__ etyp) {
    int e = blockIdx.x * blockDim.x + threadIdx.x;
    if (e >= EE) return;
    int d = edst[e], t = etyp[e];
    atomicAdd(&g_cnt[d * RR + t], 1);
    atomicAdd(&g_deg[d], 1);
}

// ---------------- 3-phase exclusive scan over NN ints ----------------
__global__ void k_scanA(const int* __restrict__ in) {
    __shared__ int sd[1024];
    int b = blockIdx.x, tid = threadIdx.x;
    int gid = b * 1024 + tid;
    int v = in[gid];
    sd[tid] = v;
    __syncthreads();
    for (int off = 1; off < 1024; off <<= 1) {
        int t = (tid >= off) ? sd[tid - off] : 0;
        __syncthreads();
        sd[tid] += t;
        __syncthreads();
    }
    g_pscan[gid] = sd[tid] - v;
    if (tid == 1023) g_btot[b] = sd[tid];
}

__global__ void k_scanB() {
    if (threadIdx.x == 0) {
        int run = 0;
        for (int i = 0; i < NBLK; i++) { g_boff[i] = run; run += g_btot[i]; }
    }
}

__global__ void k_finrow() {
    int gid = blockIdx.x * blockDim.x + threadIdx.x;
    if (gid >= NN) return;
    int e = g_pscan[gid] + g_boff[gid >> 10];
    g_rowptr[gid] = e;
    g_cursor[gid] = e;
    if (gid == 0) g_rowptr[NN] = EE;
}

__global__ void k_fill(const int* __restrict__ edst) {
    int e = blockIdx.x * blockDim.x + threadIdx.x;
    if (e >= EE) return;
    int pos = atomicAdd(&g_cursor[edst[e]], 1);
    g_eidx[pos] = e;
}

// deterministic per-bucket order: sort each bucket by edge id, then finalize payload
__global__ void k_sortfin(const int* __restrict__ esrc, const int* __restrict__ etyp) {
    int n = blockIdx.x * blockDim.x + threadIdx.x;
    if (n >= NN) return;
    int s = g_rowptr[n], t = g_rowptr[n + 1];
    for (int i = s + 1; i < t; i++) {
        int v = g_eidx[i];
        int j = i - 1;
        while (j >= s && g_eidx[j] > v) { g_eidx[j + 1] = g_eidx[j]; j--; }
        g_eidx[j + 1] = v;
    }
    for (int i = s; i < t; i++) {
        int e  = g_eidx[i];
        int et = etyp[e];
        int c  = g_cnt[n * RR + et];
        g_srow[i] = esrc[e] * RR + et;
        g_ew[i]   = 1.0f / (float)(c < 1 ? 1 : c);
    }
}

__global__ void k_qlist(const int* __restrict__ dq, const int* __restrict__ ptr) {
    int q = blockIdx.x * blockDim.x + threadIdx.x;
    if (q >= NQ) return;
    g_qo[q] = dq[q] + ptr[q];
}

// ---------------- aggregate-first: y[n,b,:] = sum_e comp[et,b]*w * h[src,:] ----------------
__device__ __forceinline__ void aggr_node(
    const float* __restrict__ hin, const float* __restrict__ sc,
    int n, int lane, float* __restrict__ yout)
{
    int s = g_rowptr[n], e = g_rowptr[n + 1];
    float4 acc[NBASE];
#pragma unroll
    for (int b = 0; b < NBASE; b++) acc[b] = make_float4(0.f, 0.f, 0.f, 0.f);
    int i = s;
    for (; i + 2 <= e; i += 2) {
        int s0 = g_srow[i],  s1 = g_srow[i + 1];
        float w0 = g_ew[i],  w1 = g_ew[i + 1];
        float4 v0 = *(const float4*)(hin + (size_t)(s0 >> 4) * HH + (lane << 2));
        float4 v1 = *(const float4*)(hin + (size_t)(s1 >> 4) * HH + (lane << 2));
        const float* c0 = sc + (s0 & 15) * NBASE;
        const float* c1 = sc + (s1 & 15) * NBASE;
#pragma unroll
        for (int b = 0; b < NBASE; b++) {
            float f0 = c0[b] * w0;
            acc[b].x += f0 * v0.x; acc[b].y += f0 * v0.y;
            acc[b].z += f0 * v0.z; acc[b].w += f0 * v0.w;
            float f1 = c1[b] * w1;
            acc[b].x += f1 * v1.x; acc[b].y += f1 * v1.y;
            acc[b].z += f1 * v1.z; acc[b].w += f1 * v1.w;
        }
    }
    if (i < e) {
        int s0 = g_srow[i];
        float w0 = g_ew[i];
        float4 v0 = *(const float4*)(hin + (size_t)(s0 >> 4) * HH + (lane << 2));
        const float* c0 = sc + (s0 & 15) * NBASE;
#pragma unroll
        for (int b = 0; b < NBASE; b++) {
            float f0 = c0[b] * w0;
            acc[b].x += f0 * v0.x; acc[b].y += f0 * v0.y;
            acc[b].z += f0 * v0.z; acc[b].w += f0 * v0.w;
        }
    }
    float* yp = yout + (lane << 2);
#pragma unroll
    for (int b = 0; b < NBASE; b++) *(float4*)(yp + b * HH) = acc[b];
}

__global__ void __launch_bounds__(256) k_aggr(const float* __restrict__ hin,
                                              const float* __restrict__ comp,
                                              float* __restrict__ y) {
    __shared__ float sc[RR * NBASE];
    int tid = threadIdx.x;
    if (tid < RR * NBASE) sc[tid] = comp[tid];
    __syncthreads();
    int warp = (blockIdx.x * blockDim.x + tid) >> 5;
    int lane = tid & 31;
    if (warp >= NN) return;
    aggr_node(hin, sc, warp, lane, y + (size_t)warp * YC);
}

__global__ void __launch_bounds__(256) k_aggr4(const float* __restrict__ hin,
                                               const float* __restrict__ comp,
                                               float* __restrict__ y4) {
    __shared__ float sc[RR * NBASE];
    int tid = threadIdx.x;
    if (tid < RR * NBASE) sc[tid] = comp[tid];
    __syncthreads();
    int warp = (blockIdx.x * blockDim.x + tid) >> 5;
    int lane = tid & 31;
    if (warp >= NQ) return;
    aggr_node(hin, sc, g_qo[warp], lane, y4 + (size_t)warp * YC);
}

// ---------------- bf16x3 GEMM: C = [A1 | A2] @ [Br ; Bb] + cbias (+relu) ----------------
// split x = hi + lo (bf16 each); C = Ah*Bh + Ah*Bl + Al*Bh  (AlBl term ~2^-17, dropped)
__device__ __forceinline__ void split2(float a, float b, uint32_t& hi, uint32_t& lo) {
    __nv_bfloat16 ah = __float2bfloat16_rn(a), bh = __float2bfloat16_rn(b);
    float ar = a - __bfloat162float(ah), br = b - __bfloat162float(bh);
    __nv_bfloat16 al = __float2bfloat16_rn(ar), bl = __float2bfloat16_rn(br);
    hi = ((uint32_t)__bfloat16_as_ushort(bh) << 16) | __bfloat16_as_ushort(ah);
    lo = ((uint32_t)__bfloat16_as_ushort(bl) << 16) | __bfloat16_as_ushort(al);
}

__device__ __forceinline__ void mma16(float* c, const uint32_t* a, const uint32_t* b) {
    asm("mma.sync.aligned.m16n8k16.row.col.f32.bf16.bf16.f32 "
        "{%0,%1,%2,%3}, {%4,%5,%6,%7}, {%8,%9}, {%0,%1,%2,%3};"
        : "+f"(c[0]), "+f"(c[1]), "+f"(c[2]), "+f"(c[3])
        : "r"(a[0]), "r"(a[1]), "r"(a[2]), "r"(a[3]), "r"(b[0]), "r"(b[1]));
}

__global__ void __launch_bounds__(512) k_gemm2(
    const float* __restrict__ A1,   // [M x 128] via rowmap (or identity)
    const float* __restrict__ A2,   // [M x 1024] logical rows
    const float* __restrict__ Br,   // [128 x 128]
    const float* __restrict__ Bb,   // [1024 x 128]
    const int* __restrict__ rowmap, // nullable (A1 rows only)
    const float* __restrict__ cbias,
    float* __restrict__ Cout, int relu)
{
    extern __shared__ uint32_t sm[];

    int tid = threadIdx.x;
    int wid = tid >> 5, lane = tid & 31;
    int wm = wid >> 2, wn = wid & 3;         // 4x4 warps, warp tile 32x32
    int grp = lane >> 2, tig = lane & 3;
    int row0 = blockIdx.x * 128;

    // A staging: thread covers rows r0,r1 at 4 consecutive k
    int r0 = tid >> 3, r1 = r0 + 64;
    int kc = (tid & 7) * 4;                  // k offset within 32-chunk
    int kc2 = kc >> 1;                       // k-pair index
    // B staging: thread covers k-pair kp at 4 consecutive cols
    int kp = tid >> 5;                       // 0..15
    int cB = (tid & 31) * 4;
    int a1r0 = rowmap ? rowmap[row0 + r0] : (row0 + r0);
    int a1r1 = rowmap ? rowmap[row0 + r1] : (row0 + r1);

    float4 av0, av1, bv0, bv1;

    auto LOAD = [&](int ci) {
        int k0 = ci * 32;
        if (k0 < 128) {
            av0 = *(const float4*)(A1 + (size_t)a1r0 * CIN + k0 + kc);
            av1 = *(const float4*)(A1 + (size_t)a1r1 * CIN + k0 + kc);
            bv0 = *(const float4*)(Br + (size_t)(k0 + 2 * kp) * HH + cB);
            bv1 = *(const float4*)(Br + (size_t)(k0 + 2 * kp + 1) * HH + cB);
        } else {
            int k2 = k0 - 128;
            av0 = *(const float4*)(A2 + (size_t)(row0 + r0) * YC + k2 + kc);
            av1 = *(const float4*)(A2 + (size_t)(row0 + r1) * YC + k2 + kc);
            bv0 = *(const float4*)(Bb + (size_t)(k2 + 2 * kp) * HH + cB);
            bv1 = *(const float4*)(Bb + (size_t)(k2 + 2 * kp + 1) * HH + cB);
        }
    };
    auto STORE = [&](int st) {
        uint32_t h0, l0, h1, l1;
        // A row r0
        split2(av0.x, av0.y, h0, l0);
        split2(av0.z, av0.w, h1, l1);
        *(uint2*)(sm + st * A_PLANE + r0 * ASTRIDE + kc2)          = make_uint2(h0, h1);
        *(uint2*)(sm + OFF_AL + st * A_PLANE + r0 * ASTRIDE + kc2) = make_uint2(l0, l1);
        // A row r1
        split2(av1.x, av1.y, h0, l0);
        split2(av1.z, av1.w, h1, l1);
        *(uint2*)(sm + st * A_PLANE + r1 * ASTRIDE + kc2)          = make_uint2(h0, h1);
        *(uint2*)(sm + OFF_AL + st * A_PLANE + r1 * ASTRIDE + kc2) = make_uint2(l0, l1);
        // B k-pair kp, 4 cols (pack along k: bv0 = even k, bv1 = odd k)
        uint32_t bh0, bl0, bh1, bl1, bh2, bl2, bh3, bl3;
        split2(bv0.x, bv1.x, bh0, bl0);
        split2(bv0.y, bv1.y, bh1, bl1);
        split2(bv0.z, bv1.z, bh2, bl2);
        split2(bv0.w, bv1.w, bh3, bl3);
        *(uint4*)(sm + OFF_BH + st * B_PLANE + kp * 136 + cB) = make_uint4(bh0, bh1, bh2, bh3);
        *(uint4*)(sm + OFF_BL + st * B_PLANE + kp * 136 + cB) = make_uint4(bl0, bl1, bl2, bl3);
    };

    float acc[2][4][4];
#pragma unroll
    for (int mi = 0; mi < 2; mi++)
#pragma unroll
        for (int ni = 0; ni < 4; ni++)
#pragma unroll
            for (int k = 0; k < 4; k++) acc[mi][ni][k] = 0.f;

    LOAD(0);
    STORE(0);
    __syncthreads();

    for (int ci = 0; ci < NCHUNK; ci++) {
        int st = ci & 1;
        if (ci + 1 < NCHUNK) LOAD(ci + 1);
        const uint32_t* sAh = sm + st * A_PLANE;
        const uint32_t* sAl = sm + OFF_AL + st * A_PLANE;
        const uint32_t* sBh = sm + OFF_BH + st * B_PLANE;
        const uint32_t* sBl = sm + OFF_BL + st * B_PLANE;
#pragma unroll
        for (int ks = 0; ks < 2; ks++) {        // two k16 steps per 32-chunk
            int kb = ks * 8;
            uint32_t bh[4][2], bl[4][2];
#pragma unroll
            for (int ni = 0; ni < 4; ni++) {
                int nc = wn * 32 + ni * 8 + grp;
                bh[ni][0] = sBh[(kb + tig) * 136 + nc];
                bh[ni][1] = sBh[(kb + tig + 4) * 136 + nc];
                bl[ni][0] = sBl[(kb + tig) * 136 + nc];
                bl[ni][1] = sBl[(kb + tig + 4) * 136 + nc];
            }
#pragma unroll
            for (int mi = 0; mi < 2; mi++) {
                int mr = wm * 32 + mi * 16 + grp;
                uint32_t ah[4], al[4];
                ah[0] = sAh[mr * ASTRIDE + kb + tig];
                ah[1] = sAh[(mr + 8) * ASTRIDE + kb + tig];
                ah[2] = sAh[mr * ASTRIDE + kb + tig + 4];
                ah[3] = sAh[(mr + 8) * ASTRIDE + kb + tig + 4];
                al[0] = sAl[mr * ASTRIDE + kb + tig];
                al[1] = sAl[(mr + 8) * ASTRIDE + kb + tig];
                al[2] = sAl[mr * ASTRIDE + kb + tig + 4];
                al[3] = sAl[(mr + 8) * ASTRIDE + kb + tig + 4];
#pragma unroll
                for (int ni = 0; ni < 4; ni++) {
                    mma16(acc[mi][ni], ah, bh[ni]);
                    mma16(acc[mi][ni], ah, bl[ni]);
                    mma16(acc[mi][ni], al, bh[ni]);
                }
            }
        }
        if (ci + 1 < NCHUNK) STORE((ci + 1) & 1);
        __syncthreads();
    }

    // epilogue: + cbias, optional relu
#pragma unroll
    for (int mi = 0; mi < 2; mi++) {
#pragma unroll
        for (int ni = 0; ni < 4; ni++) {
            int gc = wn * 32 + ni * 8 + 2 * tig;
            int r1r = row0 + wm * 32 + mi * 16 + grp;
            float b0 = __ldg(cbias + gc), b1 = __ldg(cbias + gc + 1);
            float c00 = acc[mi][ni][0] + b0, c01 = acc[mi][ni][1] + b1;
            float c10 = acc[mi][ni][2] + b0, c11 = acc[mi][ni][3] + b1;
            if (relu) {
                c00 = fmaxf(c00, 0.f); c01 = fmaxf(c01, 0.f);
                c10 = fmaxf(c10, 0.f); c11 = fmaxf(c11, 0.f);
            }
            *(float2*)(Cout + (size_t)r1r * HH + gc) = make_float2(c00, c01);
            *(float2*)(Cout + (size_t)(r1r + 8) * HH + gc) = make_float2(c10, c11);
        }
    }
}

// ---------------- head: out[q] = [h4q[q] | rel[q_rel]] @ lin_w + lin_b ----------------
__global__ void k_head(const int* __restrict__ qr,
                       const float* __restrict__ rel, const float* __restrict__ w,
                       const float* __restrict__ b, float* __restrict__ out) {
    int warp = (blockIdx.x * blockDim.x + threadIdx.x) >> 5;
    int lane = threadIdx.x & 31;
    if (warp >= NQ) return;
    const float* hv = g_h4q + (size_t)warp * HH;
    const float* rv = rel + (size_t)qr[warp] * HH;
    float s0 = 0.f, s1 = 0.f;
#pragma unroll
    for (int i = 0; i < 4; i++) {
        int k = lane + 32 * i;
        float a = hv[k], c = rv[k];
        s0 += a * w[k * 2 + 0] + c * w[(HH + k) * 2 + 0];
        s1 += a * w[k * 2 + 1] + c * w[(HH + k) * 2 + 1];
    }
#pragma unroll
    for (int off = 16; off; off >>= 1) {
        s0 += __shfl_xor_sync(0xFFFFFFFFu, s0, off);
        s1 += __shfl_xor_sync(0xFFFFFFFFu, s1, off);
    }
    if (lane == 0) {
        out[warp * 2 + 0] = s0 + b[0];
        out[warp * 2 + 1] = s1 + b[1];
    }
}

// ---------------- launch ----------------
extern "C" void kernel_launch(void* const* d_in, const int* in_sizes, int n_in,
                              void* d_out, int out_size) {
    const float* x    = (const float*)d_in[0];
    const int*   ent  = (const int*)  d_in[1];
    const int*   esrc = (const int*)  d_in[2];
    const int*   edst = (const int*)  d_in[3];
    const int*   etyp = (const int*)  d_in[4];
    const int*   dq   = (const int*)  d_in[5];
    const int*   qr   = (const int*)  d_in[6];
    const int*   ptr  = (const int*)  d_in[7];
    const float* rel  = (const float*)d_in[24];
    const float* lw   = (const float*)d_in[25];
    const float* lb   = (const float*)d_in[26];
    float*       out  = (float*)d_out;

    void* p;
    cudaGetSymbolAddress(&p, g_h0);   float* h0   = (float*)p;
    cudaGetSymbolAddress(&p, g_h1);   float* h1   = (float*)p;
    cudaGetSymbolAddress(&p, g_y);    float* yy   = (float*)p;
    cudaGetSymbolAddress(&p, g_y4);   float* y4   = (float*)p;
    cudaGetSymbolAddress(&p, g_h4q);  float* h4q  = (float*)p;
    cudaGetSymbolAddress(&p, g_cnt);  int*   cntp = (int*)p;
    cudaGetSymbolAddress(&p, g_deg);  int*   degp = (int*)p;
    cudaGetSymbolAddress(&p, g_qo);   int*   qop  = (int*)p;

    cudaFuncSetAttribute(k_gemm2, cudaFuncAttributeMaxDynamicSharedMemorySize, SMEMSZ);

    cudaMemsetAsync(cntp, 0, sizeof(int) * NN * RR, 0);
    cudaMemsetAsync(degp, 0, sizeof(int) * NN, 0);

    k_build_h0<<<(NN * CIN + 255) / 256, 256>>>(x, ent);
    k_count<<<(EE + 255) / 256, 256>>>(edst, etyp);
    k_scanA<<<NBLK, 1024>>>(degp);
    k_scanB<<<1, 32>>>();
    k_finrow<<<(NN + 255) / 256, 256>>>();
    k_fill<<<(EE + 255) / 256, 256>>>(edst);
    k_sortfin<<<(NN + 255) / 256, 256>>>(esrc, etyp);
    k_qlist<<<2, 256>>>(dq, ptr);

    float* hin = h0;
    float* hout = h1;
    for (int l = 0; l < 3; l++) {
        const float* bases = (const float*)d_in[8 + 4 * l];
        const float* comp  = (const float*)d_in[9 + 4 * l];
        const float* root  = (const float*)d_in[10 + 4 * l];
        const float* cb    = (const float*)d_in[11 + 4 * l];
        k_aggr<<<NN / 8, 256>>>(hin, comp, yy);
        k_gemm2<<<NN / 128, 512, SMEMSZ>>>(hin, yy, root, bases, nullptr, cb, hout, 1);
        float* tmp = hin; hin = hout; hout = tmp;
    }
    // layer 4: only 512 query rows
    {
        const float* bases = (const float*)d_in[20];
        const float* comp  = (const float*)d_in[21];
        const float* root  = (const float*)d_in[22];
        const float* cb    = (const float*)d_in[23];
        k_aggr4<<<NQ / 8, 256>>>(hin, comp, y4);
        k_gemm2<<<NQ / 128, 512, SMEMSZ>>>(hin, y4, root, bases, qop, cb, h4q, 0);
    }
    k_head<<<(NQ * 32 + 255) / 256, 256>>>(qr, rel, lw, lb, out);
}